// round 9
// baseline (speedup 1.0000x reference)
#include <cuda_runtime.h>
#include <cuda_fp16.h>
#include <cstdint>
#include <math.h>

// Problem constants
#define NB 2
#define NC 64
#define CI 32
#define NH 128
#define NW 128
#define NBQ 8      // b*4+q
#define NN 4096    // 64*64 spatial per quadrant
#define HW (NH*NW)
#define NT 32      // key tiles of 128
#define LOG2E 1.4426950408889634f

// Scratch (static device globals; allocation-free)
__device__ __align__(128) __half g_th [NBQ * NN * CI];   // theta*log2e [bq][n][d] fp16
__device__ __align__(128) __half g_ph [NBQ * NN * CI];   // phi   [bq][m][d] fp16
__device__ __align__(128) __half g_gxT[NBQ * CI * NN];   // g^T   [bq][d][m] fp16
__device__ __align__(128) float  g_y  [NBQ * NN * CI];   // attn out [bq][n][d] fp32
__device__ __align__(128) float  g_wy [NBQ * NC * NN];   // W*y   [bq][c][n]
__device__ float g_mu[4 * NC];
__device__ float g_rstd[4 * NC];

// ===========================================================================
// PTX helpers (all legal on compute_103)
// ===========================================================================
__device__ __forceinline__ uint32_t smem_to_u32(const void* p) {
    uint32_t a;
    asm("{ .reg .u64 t; cvta.to.shared.u64 t, %1; cvt.u32.u64 %0, t; }" : "=r"(a) : "l"(p));
    return a;
}
__device__ __forceinline__ void cp16(uint32_t s, const void* g) {
    asm volatile("cp.async.cg.shared.global [%0], [%1], 16;" :: "r"(s), "l"(g));
}
#define CP_COMMIT() asm volatile("cp.async.commit_group;" ::: "memory")
#define CP_WAIT(n)  asm volatile("cp.async.wait_group %0;" :: "n"(n) : "memory")

// 2^x on packed f16x2
__device__ __forceinline__ uint32_t ex2h2(uint32_t x) {
    uint32_t r;
    asm("ex2.approx.f16x2 %0, %1;" : "=r"(r) : "r"(x));
    return r;
}

// f32-accum MMA (for P.V)
__device__ __forceinline__ void mma_f16(float& c0, float& c1, float& c2, float& c3,
                                        uint32_t a0, uint32_t a1, uint32_t a2, uint32_t a3,
                                        uint32_t b0, uint32_t b1) {
    asm volatile(
        "mma.sync.aligned.m16n8k16.row.col.f32.f16.f16.f32 "
        "{%0,%1,%2,%3}, {%4,%5,%6,%7}, {%8,%9}, {%0,%1,%2,%3};"
        : "+f"(c0), "+f"(c1), "+f"(c2), "+f"(c3)
        : "r"(a0), "r"(a1), "r"(a2), "r"(a3), "r"(b0), "r"(b1));
}
// f16-accum MMA (for S = theta.phi^T) — D/C are f16x2 pairs, pre-packed for ex2h2
__device__ __forceinline__ void mma_f16h(uint32_t& d0, uint32_t& d1,
                                         uint32_t a0, uint32_t a1, uint32_t a2, uint32_t a3,
                                         uint32_t b0, uint32_t b1) {
    asm volatile(
        "mma.sync.aligned.m16n8k16.row.col.f16.f16.f16.f16 "
        "{%0,%1}, {%2,%3,%4,%5}, {%6,%7}, {%0,%1};"
        : "+r"(d0), "+r"(d1)
        : "r"(a0), "r"(a1), "r"(a2), "r"(a3), "r"(b0), "r"(b1));
}

// ===========================================================================
// Kernel A: fused projections (x read ONCE). theta pre-scaled by log2(e).
// grid (32 ntile, 8 bq), block 128; 96 accumulators/thread.
// ===========================================================================
__global__ __launch_bounds__(128) void proj_kernel(
    const float* __restrict__ x,
    const float* __restrict__ tw, const float* __restrict__ tb,
    const float* __restrict__ pw, const float* __restrict__ pb,
    const float* __restrict__ gw, const float* __restrict__ gb)
{
    __shared__ __align__(16) float ws[3 * NC * CI];   // [mat][c][o]
    __shared__ float bs[3 * CI];

    int tid = threadIdx.x;
    for (int i = tid; i < 3 * NC * CI; i += 128) {
        int m = i >> 11, r = i & 2047, o = r >> 6, c = r & 63;
        const float* W = (m == 0) ? tw : ((m == 1) ? pw : gw);
        float sc = (m == 0) ? LOG2E : 1.0f;
        ws[m * 2048 + c * CI + o] = W[r] * sc;
    }
    if (tid < 96) {
        int m = tid >> 5, o = tid & 31;
        const float* Bv = (m == 0) ? tb : ((m == 1) ? pb : gb);
        bs[tid] = Bv[o] * ((m == 0) ? LOG2E : 1.0f);
    }
    __syncthreads();

    int bq = blockIdx.y;
    int n  = blockIdx.x * 128 + tid;
    int b  = bq >> 2, q = bq & 3, qr = q >> 1, qc = q & 1;
    int hh = n >> 6, ww = n & 63;

    const float* xp = x + (size_t)b * NC * HW + (qr * 64 + hh) * NW + (qc * 64 + ww);

    float acc[96];
#pragma unroll
    for (int o = 0; o < 96; o++) acc[o] = bs[o];

    const float4* ws4 = (const float4*)ws;
#pragma unroll 2
    for (int c = 0; c < NC; c++) {
        float xv = xp[c * HW];
#pragma unroll
        for (int m = 0; m < 3; m++) {
#pragma unroll
            for (int o4 = 0; o4 < 8; o4++) {
                float4 w = ws4[m * 512 + c * 8 + o4];
                acc[m * 32 + o4 * 4 + 0] += w.x * xv;
                acc[m * 32 + o4 * 4 + 1] += w.y * xv;
                acc[m * 32 + o4 * 4 + 2] += w.z * xv;
                acc[m * 32 + o4 * 4 + 3] += w.w * xv;
            }
        }
    }

    {   // theta, phi: row-major fp16
        __half* opt = g_th + ((size_t)bq * NN + n) * CI;
        __half* opp = g_ph + ((size_t)bq * NN + n) * CI;
#pragma unroll
        for (int o = 0; o < CI; o += 2) {
            *(__half2*)(opt + o) = __floats2half2_rn(acc[o], acc[o + 1]);
            *(__half2*)(opp + o) = __floats2half2_rn(acc[32 + o], acc[32 + o + 1]);
        }
        // g: transposed fp16 [d][m]
        __half* opg = g_gxT + (size_t)bq * CI * NN + n;
#pragma unroll
        for (int o = 0; o < CI; o++) opg[(size_t)o * NN] = __float2half_rn(acc[64 + o]);
    }
}

// ===========================================================================
// Kernel B: fp16 m16n8k16 flash attention.
// S in f16 accumulators (pre-packed for ex2.f16x2); PV in f32 accumulators.
// Row sums on the idle fma pipe (HADD2 + f32 promote per nbp).
// grid (32 q-tiles, 8 bq), block 256 (8 warps x 16 rows)
// ===========================================================================
#define PH2 20                         // phi row stride in b32 words (16 data + 4 pad)
#define VT2 68                         // v^T row stride in b32 words (64 data + 4 pad)
#define PHI_WORDS (128 * PH2)          // 2560
#define VT_WORDS  (32 * VT2)           // 2176
#define BUF_WORDS (PHI_WORDS + VT_WORDS)  // 4736
#define PHI_BYTES (PHI_WORDS * 4)
#define BUF_BYTES (BUF_WORDS * 4)      // 18944
#define SMEM_TOTAL (2 * BUF_BYTES)     // 37888

__global__ void __launch_bounds__(256, 2) attn_mma_kernel()
{
    extern __shared__ uint32_t smw[];
    uint32_t sb = smem_to_u32(smw);
    int tid = threadIdx.x, wid = tid >> 5, lane = tid & 31;
    int g = lane >> 2, tig = lane & 3;               // row-group, thread-in-group
    int bq = blockIdx.y, qt = blockIdx.x;

    const __half* phg = g_ph  + (size_t)bq * NN * CI;
    const __half* vtg = g_gxT + (size_t)bq * CI * NN;

    // ---- theta A fragments (m16n8k16): rows wid*16+{g,g+8}, k-words per MMA ----
    uint32_t aS[2][4];
    {
        const __half* thp = g_th + ((size_t)bq * NN + qt * 128 + wid * 16) * CI;
#pragma unroll
        for (int kk = 0; kk < 2; kk++) {
            aS[kk][0] = *(const uint32_t*)(thp + (size_t)g       * CI + (tig + 8 * kk) * 2);
            aS[kk][1] = *(const uint32_t*)(thp + (size_t)(g + 8) * CI + (tig + 8 * kk) * 2);
            aS[kk][2] = *(const uint32_t*)(thp + (size_t)g       * CI + (tig + 4 + 8 * kk) * 2);
            aS[kk][3] = *(const uint32_t*)(thp + (size_t)(g + 8) * CI + (tig + 4 + 8 * kk) * 2);
        }
    }

    // ---- stage helper: tile t -> buffer buf (phi rows + v^T rows), cp.async ----
    auto stage = [&](int t, int buf) {
        uint32_t base = sb + (uint32_t)buf * BUF_BYTES;
        const __half* pg = phg + (size_t)t * 128 * CI;
#pragma unroll
        for (int cc = 0; cc < 2; cc++) {
            int idx = tid + cc * 256;            // 0..511
            int row = idx >> 2, ch = idx & 3;    // phi: 128 rows x 4 chunks of 16B
            cp16(base + (uint32_t)(row * PH2 + ch * 4) * 4u, pg + (size_t)row * CI + ch * 8);
            int d = idx >> 4, kc = idx & 15;     // v^T: 32 rows x 16 chunks of 16B
            cp16(base + PHI_BYTES + (uint32_t)(d * VT2 + kc * 4) * 4u,
                 vtg + (size_t)d * NN + t * 128 + kc * 8);
        }
    };

    stage(0, 0);
    CP_COMMIT();

    float o0[4] = {0,0,0,0}, o1[4] = {0,0,0,0}, o2[4] = {0,0,0,0}, o3[4] = {0,0,0,0};
    float lsum0 = 0.0f, lsum1 = 0.0f;

    for (int t = 0; t < NT; t++) {
        int cur = t & 1;
        if (t + 1 < NT) {
            stage(t + 1, cur ^ 1);
            CP_COMMIT();
            CP_WAIT(1);
        } else {
            CP_WAIT(0);
        }
        __syncthreads();

        const uint32_t* psw = smw + (size_t)cur * BUF_WORDS;
        const uint32_t* vtw = psw + PHI_WORDS;

#pragma unroll
        for (int nbp = 0; nbp < 8; nbp++) {
            // ---- S (f16 accum, pre-packed) for key block 2*nbp, then ex2 ----
            uint32_t a0, a1, a2, a3;
            {
                uint32_t s0 = 0, s1 = 0;
                const uint32_t* prow = psw + (nbp * 16 + g) * PH2;
                mma_f16h(s0, s1, aS[0][0], aS[0][1], aS[0][2], aS[0][3],
                         prow[tig], prow[tig + 4]);
                mma_f16h(s0, s1, aS[1][0], aS[1][1], aS[1][2], aS[1][3],
                         prow[tig + 8], prow[tig + 12]);
                a0 = ex2h2(s0);   // P row g,   keys {2tig,2tig+1} of block 2nbp
                a1 = ex2h2(s1);   // P row g+8
            }
            // ---- S for key block 2*nbp+1 ----
            {
                uint32_t s0 = 0, s1 = 0;
                const uint32_t* prow = psw + (nbp * 16 + 8 + g) * PH2;
                mma_f16h(s0, s1, aS[0][0], aS[0][1], aS[0][2], aS[0][3],
                         prow[tig], prow[tig + 4]);
                mma_f16h(s0, s1, aS[1][0], aS[1][1], aS[1][2], aS[1][3],
                         prow[tig + 8], prow[tig + 12]);
                a2 = ex2h2(s0);
                a3 = ex2h2(s1);
            }
            // ---- row sums on fma pipe (f32-promoted per nbp) ----
            {
                __half2 hg = __hadd2(*(__half2*)&a0, *(__half2*)&a2);  // row g
                __half2 hb = __hadd2(*(__half2*)&a1, *(__half2*)&a3);  // row g+8
                float2 fg = __half22float2(hg);
                float2 fb = __half22float2(hb);
                lsum0 += fg.x + fg.y;
                lsum1 += fb.x + fb.y;
            }
            // ---- O += P(16 x k16) . V(k16 x 32): 4 d-blocks (f32 accum) ----
            {
                const uint32_t* v0 = vtw + g * VT2 + nbp * 8;
                mma_f16(o0[0], o0[1], o0[2], o0[3], a0, a1, a2, a3, v0[tig], v0[tig + 4]);
                const uint32_t* v1 = vtw + (g + 8) * VT2 + nbp * 8;
                mma_f16(o1[0], o1[1], o1[2], o1[3], a0, a1, a2, a3, v1[tig], v1[tig + 4]);
                const uint32_t* v2 = vtw + (g + 16) * VT2 + nbp * 8;
                mma_f16(o2[0], o2[1], o2[2], o2[3], a0, a1, a2, a3, v2[tig], v2[tig + 4]);
                const uint32_t* v3 = vtw + (g + 24) * VT2 + nbp * 8;
                mma_f16(o3[0], o3[1], o3[2], o3[3], a0, a1, a2, a3, v3[tig], v3[tig + 4]);
            }
        }
        __syncthreads();   // all warps done with buf before it is restaged
    }

    // ---- reduce row sums across the 4 lanes of each row group ----
    lsum0 += __shfl_xor_sync(0xFFFFFFFFu, lsum0, 1);
    lsum0 += __shfl_xor_sync(0xFFFFFFFFu, lsum0, 2);
    lsum1 += __shfl_xor_sync(0xFFFFFFFFu, lsum1, 1);
    lsum1 += __shfl_xor_sync(0xFFFFFFFFu, lsum1, 2);
    float inv0 = 1.0f / lsum0;
    float inv1 = 1.0f / lsum1;

    // ---- writeback: row g -> (c0,c1), row g+8 -> (c2,c3) per d-block ----
    {
        int row0 = qt * 128 + wid * 16 + g;
        float* y0 = g_y + ((size_t)bq * NN + row0) * CI;
        float* y1 = y0 + 8 * CI;
        float* ob[4] = {o0, o1, o2, o3};
#pragma unroll
        for (int j = 0; j < 4; j++) {
            *(float2*)(y0 + j * 8 + 2 * tig) = make_float2(ob[j][0] * inv0, ob[j][1] * inv0);
            *(float2*)(y1 + j * 8 + 2 * tig) = make_float2(ob[j][2] * inv1, ob[j][3] * inv1);
        }
    }
}

// ===========================================================================
// Kernel C: wy[bq][c][n] = w_w[c][:] . y[bq][n][:] + w_b[c]
// ===========================================================================
__global__ __launch_bounds__(256) void wy_kernel(
    const float* __restrict__ w_w, const float* __restrict__ w_b)
{
    __shared__ __align__(16) float ys[128 * CI];
    __shared__ __align__(16) float wws[NC * CI];

    int bq = blockIdx.y;
    int n0 = blockIdx.x * 128;
    int tid = threadIdx.x;

    for (int i = tid; i < NC * CI; i += 256) wws[i] = w_w[i];
    {
        const float4* src = (const float4*)(g_y + ((size_t)bq * NN + n0) * CI);
        float4* dst = (float4*)ys;
#pragma unroll
        for (int i = 0; i < 4; i++) dst[tid + i * 256] = src[tid + i * 256];
    }
    __syncthreads();

    int n = tid & 127;
    int chalf = (tid >> 7) * 32;

    float yr[CI];
#pragma unroll
    for (int o = 0; o < CI; o++) yr[o] = ys[n * CI + o];

    const float4* wws4 = (const float4*)wws;
    float* wyp = g_wy + (size_t)bq * NC * NN + n0 + n;
    for (int cc = 0; cc < 32; cc++) {
        int c = chalf + cc;
        float a = w_b[c];
#pragma unroll
        for (int o4 = 0; o4 < 8; o4++) {
            float4 w = wws4[c * 8 + o4];
            a += w.x * yr[o4 * 4 + 0] + w.y * yr[o4 * 4 + 1]
               + w.z * yr[o4 * 4 + 2] + w.w * yr[o4 * 4 + 3];
        }
        wyp[(size_t)c * NN] = a;
    }
}

// ===========================================================================
// Kernel E: per-(q,c) BN stats over (b,n) — 512 threads, float4 loads
// ===========================================================================
__global__ __launch_bounds__(512) void stats_kernel()
{
    int q = blockIdx.x >> 6, c = blockIdx.x & 63;
    int tid = threadIdx.x;
    float s = 0.0f, s2 = 0.0f;
#pragma unroll
    for (int b = 0; b < NB; b++) {
        const float4* p = (const float4*)(g_wy + (((size_t)(b * 4 + q) * NC) + c) * NN);
#pragma unroll
        for (int i = 0; i < 2; i++) {
            float4 v = p[tid + i * 512];
            s  += v.x + v.y + v.z + v.w;
            s2 += v.x * v.x + v.y * v.y + v.z * v.z + v.w * v.w;
        }
    }
    __shared__ float rs[512], rs2[512];
    rs[tid] = s; rs2[tid] = s2;
    __syncthreads();
    for (int st = 256; st > 0; st >>= 1) {
        if (tid < st) { rs[tid] += rs[tid + st]; rs2[tid] += rs2[tid + st]; }
        __syncthreads();
    }
    if (tid == 0) {
        float mu  = rs[0] * (1.0f / 8192.0f);
        float var = rs2[0] * (1.0f / 8192.0f) - mu * mu;
        g_mu[blockIdx.x]   = mu;
        g_rstd[blockIdx.x] = rsqrtf(var + 1e-5f);
    }
}

// ===========================================================================
// Kernel D: out = bn(wy)*gamma + beta + x
// ===========================================================================
__global__ __launch_bounds__(256) void out_kernel(
    const float* __restrict__ x,
    const float* __restrict__ gamma, const float* __restrict__ beta,
    float* __restrict__ out)
{
    int idx = blockIdx.x * 256 + threadIdx.x;
    int b   = idx >> 20;
    int rem = idx & 0xFFFFF;
    int c   = rem >> 14;
    int pos = rem & 0x3FFF;
    int h = pos >> 7, w = pos & 127;
    int q = ((h >> 6) << 1) | (w >> 6);
    int n = ((h & 63) << 6) | (w & 63);
    int bq = b * 4 + q;

    float v = g_wy[(((size_t)bq * NC) + c) * NN + n];
    int qc = q * NC + c;
    out[idx] = (v - g_mu[qc]) * g_rstd[qc] * gamma[c] + beta[c] + x[idx];
}

// ===========================================================================
// Launch
// ===========================================================================
extern "C" void kernel_launch(void* const* d_in, const int* in_sizes, int n_in,
                              void* d_out, int out_size)
{
    const float* x   = (const float*)d_in[0];
    const float* gw  = (const float*)d_in[1];
    const float* gb  = (const float*)d_in[2];
    const float* tw  = (const float*)d_in[3];
    const float* tb  = (const float*)d_in[4];
    const float* pw  = (const float*)d_in[5];
    const float* pb  = (const float*)d_in[6];
    const float* ww  = (const float*)d_in[7];
    const float* wb  = (const float*)d_in[8];
    const float* bng = (const float*)d_in[9];
    const float* bnb = (const float*)d_in[10];
    float* out = (float*)d_out;

    cudaFuncSetAttribute(attn_mma_kernel,
                         cudaFuncAttributeMaxDynamicSharedMemorySize, SMEM_TOTAL);

    dim3 gA(32, 8);
    proj_kernel<<<gA, 128>>>(x, tw, tb, pw, pb, gw, gb);

    dim3 gB(32, 8);
    attn_mma_kernel<<<gB, 256, SMEM_TOTAL>>>();

    dim3 gC(32, 8);
    wy_kernel<<<gC, 256>>>(ww, wb);

    stats_kernel<<<256, 512>>>();

    out_kernel<<<8192, 256>>>(x, bng, bnb, out);
}

// round 10
// speedup vs baseline: 1.0545x; 1.0545x over previous
#include <cuda_runtime.h>
#include <cuda_fp16.h>
#include <cstdint>
#include <math.h>

// Problem constants
#define NB 2
#define NC 64
#define CI 32
#define NH 128
#define NW 128
#define NBQ 8      // b*4+q
#define NN 4096    // 64*64 spatial per quadrant
#define HW (NH*NW)
#define NT 32      // key tiles of 128
#define LOG2E 1.4426950408889634f

// Scratch (static device globals; allocation-free)
__device__ __align__(128) __half g_th [NBQ * NN * CI];   // theta*log2e [bq][n][d] fp16
__device__ __align__(128) __half g_ph [NBQ * NN * CI];   // phi   [bq][m][d] fp16
__device__ __align__(128) __half g_gxT[NBQ * CI * NN];   // g^T   [bq][d][m] fp16
__device__ __align__(128) float  g_y  [NBQ * NN * CI];   // attn out [bq][n][d] fp32
__device__ __align__(128) float  g_wy [NBQ * NC * NN];   // W*y   [bq][c][n]
__device__ float g_mu[4 * NC];
__device__ float g_rstd[4 * NC];

// ===========================================================================
// PTX helpers (all legal on compute_103)
// ===========================================================================
__device__ __forceinline__ uint32_t smem_to_u32(const void* p) {
    uint32_t a;
    asm("{ .reg .u64 t; cvta.to.shared.u64 t, %1; cvt.u32.u64 %0, t; }" : "=r"(a) : "l"(p));
    return a;
}
__device__ __forceinline__ void cp16(uint32_t s, const void* g) {
    asm volatile("cp.async.cg.shared.global [%0], [%1], 16;" :: "r"(s), "l"(g));
}
#define CP_COMMIT() asm volatile("cp.async.commit_group;" ::: "memory")
#define CP_WAIT(n)  asm volatile("cp.async.wait_group %0;" :: "n"(n) : "memory")

// 2^x on packed f16x2
__device__ __forceinline__ uint32_t ex2h2(uint32_t x) {
    uint32_t r;
    asm("ex2.approx.f16x2 %0, %1;" : "=r"(r) : "r"(x));
    return r;
}

// f32-accum MMA (for P.V)
__device__ __forceinline__ void mma_f16(float& c0, float& c1, float& c2, float& c3,
                                        uint32_t a0, uint32_t a1, uint32_t a2, uint32_t a3,
                                        uint32_t b0, uint32_t b1) {
    asm volatile(
        "mma.sync.aligned.m16n8k16.row.col.f32.f16.f16.f32 "
        "{%0,%1,%2,%3}, {%4,%5,%6,%7}, {%8,%9}, {%0,%1,%2,%3};"
        : "+f"(c0), "+f"(c1), "+f"(c2), "+f"(c3)
        : "r"(a0), "r"(a1), "r"(a2), "r"(a3), "r"(b0), "r"(b1));
}
// f16-accum MMA (for S = theta.phi^T) — D comes out pre-packed for ex2h2
__device__ __forceinline__ void mma_f16h(uint32_t& d0, uint32_t& d1,
                                         uint32_t a0, uint32_t a1, uint32_t a2, uint32_t a3,
                                         uint32_t b0, uint32_t b1) {
    asm volatile(
        "mma.sync.aligned.m16n8k16.row.col.f16.f16.f16.f16 "
        "{%0,%1}, {%2,%3,%4,%5}, {%6,%7}, {%0,%1};"
        : "+r"(d0), "+r"(d1)
        : "r"(a0), "r"(a1), "r"(a2), "r"(a3), "r"(b0), "r"(b1));
}

// ===========================================================================
// Kernel A: projections (split per-matrix; proven R8 version).
// theta pre-scaled by log2(e); g written transposed fp16 [d][m].
// ===========================================================================
__global__ __launch_bounds__(128) void proj_kernel(
    const float* __restrict__ x,
    const float* __restrict__ tw, const float* __restrict__ tb,
    const float* __restrict__ pw, const float* __restrict__ pb,
    const float* __restrict__ gw, const float* __restrict__ gb)
{
    __shared__ __align__(16) float ws[NC * CI];
    __shared__ float bs[CI];

    int mat = blockIdx.y;
    const float* W  = (mat == 0) ? tw : ((mat == 1) ? pw : gw);
    const float* Bv = (mat == 0) ? tb : ((mat == 1) ? pb : gb);
    float scale = (mat == 0) ? LOG2E : 1.0f;

    int tid = threadIdx.x;
    for (int i = tid; i < CI * NC; i += 128) {
        int o = i >> 6, c = i & 63;
        ws[c * CI + o] = W[i] * scale;
    }
    if (tid < CI) bs[tid] = Bv[tid] * scale;
    __syncthreads();

    int bq = blockIdx.z;
    int n  = blockIdx.x * 128 + tid;
    int b  = bq >> 2, q = bq & 3, qr = q >> 1, qc = q & 1;
    int hh = n >> 6, ww = n & 63;

    const float* xp = x + (size_t)b * NC * HW + (qr * 64 + hh) * NW + (qc * 64 + ww);

    float acc[CI];
#pragma unroll
    for (int o = 0; o < CI; o++) acc[o] = bs[o];

    const float4* ws4 = (const float4*)ws;
#pragma unroll 4
    for (int c = 0; c < NC; c++) {
        float xv = xp[c * HW];
#pragma unroll
        for (int o4 = 0; o4 < 8; o4++) {
            float4 w = ws4[c * 8 + o4];
            acc[o4 * 4 + 0] += w.x * xv;
            acc[o4 * 4 + 1] += w.y * xv;
            acc[o4 * 4 + 2] += w.z * xv;
            acc[o4 * 4 + 3] += w.w * xv;
        }
    }

    if (mat == 2) {
        __half* op = g_gxT + (size_t)bq * CI * NN + n;
#pragma unroll
        for (int o = 0; o < CI; o++) op[(size_t)o * NN] = __float2half_rn(acc[o]);
    } else {
        __half* op = ((mat == 0) ? g_th : g_ph) + ((size_t)bq * NN + n) * CI;
#pragma unroll
        for (int o = 0; o < CI; o += 2) {
            __half2 h2 = __floats2half2_rn(acc[o], acc[o + 1]);
            *(__half2*)(op + o) = h2;
        }
    }
}

// ===========================================================================
// Kernel B: fp16 flash attention, M=32 rows per warp (two m16 A-groups).
// Every phi/V B-fragment loaded from smem feeds TWO MMAs -> LDS bytes halved.
// grid (16 q-tiles of 256 rows, 8 bq), block 256 (8 warps x 32 rows)
// ===========================================================================
#define PH2 20                         // phi row stride in b32 words (16 data + 4 pad)
#define VT2 68                         // v^T row stride in b32 words (64 data + 4 pad)
#define PHI_WORDS (128 * PH2)          // 2560
#define VT_WORDS  (32 * VT2)           // 2176
#define BUF_WORDS (PHI_WORDS + VT_WORDS)  // 4736
#define PHI_BYTES (PHI_WORDS * 4)
#define BUF_BYTES (BUF_WORDS * 4)      // 18944
#define SMEM_TOTAL (2 * BUF_BYTES)     // 37888

__global__ void __launch_bounds__(256, 2) attn_mma_kernel()
{
    extern __shared__ uint32_t smw[];
    uint32_t sb = smem_to_u32(smw);
    int tid = threadIdx.x, wid = tid >> 5, lane = tid & 31;
    int g = lane >> 2, tig = lane & 3;               // row-group, thread-in-group
    int bq = blockIdx.y, qt = blockIdx.x;

    const __half* phg = g_ph  + (size_t)bq * NN * CI;
    const __half* vtg = g_gxT + (size_t)bq * CI * NN;

    // ---- theta A fragments: two 16-row groups (rows qt*256 + wid*32 + grp*16) ----
    uint32_t aS[2][2][4];
#pragma unroll
    for (int grp = 0; grp < 2; grp++) {
        const __half* thp = g_th + ((size_t)bq * NN + qt * 256 + wid * 32 + grp * 16) * CI;
#pragma unroll
        for (int kk = 0; kk < 2; kk++) {
            aS[grp][kk][0] = *(const uint32_t*)(thp + (size_t)g       * CI + (tig + 8 * kk) * 2);
            aS[grp][kk][1] = *(const uint32_t*)(thp + (size_t)(g + 8) * CI + (tig + 8 * kk) * 2);
            aS[grp][kk][2] = *(const uint32_t*)(thp + (size_t)g       * CI + (tig + 4 + 8 * kk) * 2);
            aS[grp][kk][3] = *(const uint32_t*)(thp + (size_t)(g + 8) * CI + (tig + 4 + 8 * kk) * 2);
        }
    }

    // ---- stage helper: tile t -> buffer buf (phi rows + v^T rows), cp.async ----
    auto stage = [&](int t, int buf) {
        uint32_t base = sb + (uint32_t)buf * BUF_BYTES;
        const __half* pg = phg + (size_t)t * 128 * CI;
#pragma unroll
        for (int cc = 0; cc < 2; cc++) {
            int idx = tid + cc * 256;            // 0..511
            int row = idx >> 2, ch = idx & 3;    // phi: 128 rows x 4 chunks of 16B
            cp16(base + (uint32_t)(row * PH2 + ch * 4) * 4u, pg + (size_t)row * CI + ch * 8);
            int d = idx >> 4, kc = idx & 15;     // v^T: 32 rows x 16 chunks of 16B
            cp16(base + PHI_BYTES + (uint32_t)(d * VT2 + kc * 4) * 4u,
                 vtg + (size_t)d * NN + t * 128 + kc * 8);
        }
    };

    stage(0, 0);
    CP_COMMIT();

    float o[2][4][4];
#pragma unroll
    for (int grp = 0; grp < 2; grp++)
#pragma unroll
        for (int d = 0; d < 4; d++)
#pragma unroll
            for (int j = 0; j < 4; j++) o[grp][d][j] = 0.0f;
    float ls[2][2] = {{0.0f, 0.0f}, {0.0f, 0.0f}};

    for (int t = 0; t < NT; t++) {
        int cur = t & 1;
        if (t + 1 < NT) {
            stage(t + 1, cur ^ 1);
            CP_COMMIT();
            CP_WAIT(1);
        } else {
            CP_WAIT(0);
        }
        __syncthreads();

        const uint32_t* psw = smw + (size_t)cur * BUF_WORDS;
        const uint32_t* vtw = psw + PHI_WORDS;

#pragma unroll
        for (int nbp = 0; nbp < 8; nbp++) {
            // ---- load phi B-fragments ONCE for both key blocks ----
            const uint32_t* prow0 = psw + (nbp * 16 + g) * PH2;
            const uint32_t* prow1 = psw + (nbp * 16 + 8 + g) * PH2;
            uint32_t p00 = prow0[tig], p01 = prow0[tig + 4];
            uint32_t p02 = prow0[tig + 8], p03 = prow0[tig + 12];
            uint32_t p10 = prow1[tig], p11 = prow1[tig + 4];
            uint32_t p12 = prow1[tig + 8], p13 = prow1[tig + 12];

            uint32_t A[2][4];
#pragma unroll
            for (int grp = 0; grp < 2; grp++) {
                uint32_t s0 = 0, s1 = 0;
                mma_f16h(s0, s1, aS[grp][0][0], aS[grp][0][1], aS[grp][0][2], aS[grp][0][3],
                         p00, p01);
                mma_f16h(s0, s1, aS[grp][1][0], aS[grp][1][1], aS[grp][1][2], aS[grp][1][3],
                         p02, p03);
                uint32_t t0 = 0, t1 = 0;
                mma_f16h(t0, t1, aS[grp][0][0], aS[grp][0][1], aS[grp][0][2], aS[grp][0][3],
                         p10, p11);
                mma_f16h(t0, t1, aS[grp][1][0], aS[grp][1][1], aS[grp][1][2], aS[grp][1][3],
                         p12, p13);
                A[grp][0] = ex2h2(s0);   // row g,   keys of block 2nbp
                A[grp][1] = ex2h2(s1);   // row g+8, keys of block 2nbp
                A[grp][2] = ex2h2(t0);   // row g,   keys of block 2nbp+1
                A[grp][3] = ex2h2(t1);   // row g+8
                // row sums on fma pipe
                __half2 hg = __hadd2(*(__half2*)&A[grp][0], *(__half2*)&A[grp][2]);
                __half2 hb = __hadd2(*(__half2*)&A[grp][1], *(__half2*)&A[grp][3]);
                float2 fg = __half22float2(hg);
                float2 fb = __half22float2(hb);
                ls[grp][0] += fg.x + fg.y;
                ls[grp][1] += fb.x + fb.y;
            }
            // ---- load V B-fragments ONCE per d-block; feed both groups ----
#pragma unroll
            for (int d = 0; d < 4; d++) {
                const uint32_t* v = vtw + (g + 8 * d) * VT2 + nbp * 8;
                uint32_t vb0 = v[tig], vb1 = v[tig + 4];
                mma_f16(o[0][d][0], o[0][d][1], o[0][d][2], o[0][d][3],
                        A[0][0], A[0][1], A[0][2], A[0][3], vb0, vb1);
                mma_f16(o[1][d][0], o[1][d][1], o[1][d][2], o[1][d][3],
                        A[1][0], A[1][1], A[1][2], A[1][3], vb0, vb1);
            }
        }
        __syncthreads();   // all warps done with buf before it is restaged
    }

    // ---- finalize both groups ----
#pragma unroll
    for (int grp = 0; grp < 2; grp++) {
        float l0 = ls[grp][0], l1 = ls[grp][1];
        l0 += __shfl_xor_sync(0xFFFFFFFFu, l0, 1);
        l0 += __shfl_xor_sync(0xFFFFFFFFu, l0, 2);
        l1 += __shfl_xor_sync(0xFFFFFFFFu, l1, 1);
        l1 += __shfl_xor_sync(0xFFFFFFFFu, l1, 2);
        float inv0 = 1.0f / l0;
        float inv1 = 1.0f / l1;

        int row0 = qt * 256 + wid * 32 + grp * 16 + g;
        float* y0 = g_y + ((size_t)bq * NN + row0) * CI;
        float* y1 = y0 + 8 * CI;
#pragma unroll
        for (int j = 0; j < 4; j++) {
            *(float2*)(y0 + j * 8 + 2 * tig) =
                make_float2(o[grp][j][0] * inv0, o[grp][j][1] * inv0);
            *(float2*)(y1 + j * 8 + 2 * tig) =
                make_float2(o[grp][j][2] * inv1, o[grp][j][3] * inv1);
        }
    }
}

// ===========================================================================
// Kernel C: wy[bq][c][n] = w_w[c][:] . y[bq][n][:] + w_b[c]
// ===========================================================================
__global__ __launch_bounds__(256) void wy_kernel(
    const float* __restrict__ w_w, const float* __restrict__ w_b)
{
    __shared__ __align__(16) float ys[128 * CI];
    __shared__ __align__(16) float wws[NC * CI];

    int bq = blockIdx.y;
    int n0 = blockIdx.x * 128;
    int tid = threadIdx.x;

    for (int i = tid; i < NC * CI; i += 256) wws[i] = w_w[i];
    {
        const float4* src = (const float4*)(g_y + ((size_t)bq * NN + n0) * CI);
        float4* dst = (float4*)ys;
#pragma unroll
        for (int i = 0; i < 4; i++) dst[tid + i * 256] = src[tid + i * 256];
    }
    __syncthreads();

    int n = tid & 127;
    int chalf = (tid >> 7) * 32;

    float yr[CI];
#pragma unroll
    for (int o = 0; o < CI; o++) yr[o] = ys[n * CI + o];

    const float4* wws4 = (const float4*)wws;
    float* wyp = g_wy + (size_t)bq * NC * NN + n0 + n;
    for (int cc = 0; cc < 32; cc++) {
        int c = chalf + cc;
        float a = w_b[c];
#pragma unroll
        for (int o4 = 0; o4 < 8; o4++) {
            float4 w = wws4[c * 8 + o4];
            a += w.x * yr[o4 * 4 + 0] + w.y * yr[o4 * 4 + 1]
               + w.z * yr[o4 * 4 + 2] + w.w * yr[o4 * 4 + 3];
        }
        wyp[(size_t)c * NN] = a;
    }
}

// ===========================================================================
// Kernel E: per-(q,c) BN stats over (b,n) — 512 threads, float4 loads
// ===========================================================================
__global__ __launch_bounds__(512) void stats_kernel()
{
    int q = blockIdx.x >> 6, c = blockIdx.x & 63;
    int tid = threadIdx.x;
    float s = 0.0f, s2 = 0.0f;
#pragma unroll
    for (int b = 0; b < NB; b++) {
        const float4* p = (const float4*)(g_wy + (((size_t)(b * 4 + q) * NC) + c) * NN);
#pragma unroll
        for (int i = 0; i < 2; i++) {
            float4 v = p[tid + i * 512];
            s  += v.x + v.y + v.z + v.w;
            s2 += v.x * v.x + v.y * v.y + v.z * v.z + v.w * v.w;
        }
    }
    __shared__ float rs[512], rs2[512];
    rs[tid] = s; rs2[tid] = s2;
    __syncthreads();
    for (int st = 256; st > 0; st >>= 1) {
        if (tid < st) { rs[tid] += rs[tid + st]; rs2[tid] += rs2[tid + st]; }
        __syncthreads();
    }
    if (tid == 0) {
        float mu  = rs[0] * (1.0f / 8192.0f);
        float var = rs2[0] * (1.0f / 8192.0f) - mu * mu;
        g_mu[blockIdx.x]   = mu;
        g_rstd[blockIdx.x] = rsqrtf(var + 1e-5f);
    }
}

// ===========================================================================
// Kernel D: out = bn(wy)*gamma + beta + x
// ===========================================================================
__global__ __launch_bounds__(256) void out_kernel(
    const float* __restrict__ x,
    const float* __restrict__ gamma, const float* __restrict__ beta,
    float* __restrict__ out)
{
    int idx = blockIdx.x * 256 + threadIdx.x;
    int b   = idx >> 20;
    int rem = idx & 0xFFFFF;
    int c   = rem >> 14;
    int pos = rem & 0x3FFF;
    int h = pos >> 7, w = pos & 127;
    int q = ((h >> 6) << 1) | (w >> 6);
    int n = ((h & 63) << 6) | (w & 63);
    int bq = b * 4 + q;

    float v = g_wy[(((size_t)bq * NC) + c) * NN + n];
    int qc = q * NC + c;
    out[idx] = (v - g_mu[qc]) * g_rstd[qc] * gamma[c] + beta[c] + x[idx];
}

// ===========================================================================
// Launch
// ===========================================================================
extern "C" void kernel_launch(void* const* d_in, const int* in_sizes, int n_in,
                              void* d_out, int out_size)
{
    const float* x   = (const float*)d_in[0];
    const float* gw  = (const float*)d_in[1];
    const float* gb  = (const float*)d_in[2];
    const float* tw  = (const float*)d_in[3];
    const float* tb  = (const float*)d_in[4];
    const float* pw  = (const float*)d_in[5];
    const float* pb  = (const float*)d_in[6];
    const float* ww  = (const float*)d_in[7];
    const float* wb  = (const float*)d_in[8];
    const float* bng = (const float*)d_in[9];
    const float* bnb = (const float*)d_in[10];
    float* out = (float*)d_out;

    cudaFuncSetAttribute(attn_mma_kernel,
                         cudaFuncAttributeMaxDynamicSharedMemorySize, SMEM_TOTAL);

    dim3 gA(32, 3, 8);
    proj_kernel<<<gA, 128>>>(x, tw, tb, pw, pb, gw, gb);

    dim3 gB(16, 8);
    attn_mma_kernel<<<gB, 256, SMEM_TOTAL>>>();

    dim3 gC(32, 8);
    wy_kernel<<<gC, 256>>>(ww, wb);

    stats_kernel<<<256, 512>>>();

    out_kernel<<<8192, 256>>>(x, bng, bnb, out);
}

// round 12
// speedup vs baseline: 1.1033x; 1.0463x over previous
#include <cuda_runtime.h>
#include <cuda_fp16.h>
#include <cstdint>
#include <math.h>

// Problem constants
#define NB 2
#define NC 64
#define CI 32
#define NH 128
#define NW 128
#define NBQ 8      // b*4+q
#define NN 4096    // 64*64 spatial per quadrant
#define HW (NH*NW)
#define NT 32      // key tiles of 128
#define LOG2E 1.4426950408889634f

// Scratch (static device globals; allocation-free)
__device__ __align__(128) __half g_th [NBQ * NN * CI];   // theta*log2e [bq][n][d] fp16
__device__ __align__(128) __half g_ph [NBQ * NN * CI];   // phi   [bq][m][d] fp16
__device__ __align__(128) __half g_gxT[NBQ * CI * NN];   // g^T   [bq][d][m] fp16
__device__ __align__(128) float  g_y  [NBQ * NN * CI];   // attn out [bq][n][d] fp32
__device__ __align__(128) float  g_wy [NBQ * NC * NN];   // W*y   [bq][c][n]
__device__ float g_mu[4 * NC];
__device__ float g_rstd[4 * NC];

// ===========================================================================
// PTX helpers (all legal on compute_103)
// ===========================================================================
__device__ __forceinline__ uint32_t smem_to_u32(const void* p) {
    uint32_t a;
    asm("{ .reg .u64 t; cvta.to.shared.u64 t, %1; cvt.u32.u64 %0, t; }" : "=r"(a) : "l"(p));
    return a;
}
__device__ __forceinline__ void cp16(uint32_t s, const void* g) {
    asm volatile("cp.async.cg.shared.global [%0], [%1], 16;" :: "r"(s), "l"(g));
}
#define CP_COMMIT() asm volatile("cp.async.commit_group;" ::: "memory")
#define CP_WAIT(n)  asm volatile("cp.async.wait_group %0;" :: "n"(n) : "memory")

// 2^x on packed f16x2
__device__ __forceinline__ uint32_t ex2h2(uint32_t x) {
    uint32_t r;
    asm("ex2.approx.f16x2 %0, %1;" : "=r"(r) : "r"(x));
    return r;
}

// f32-accum MMA (for P.V)
__device__ __forceinline__ void mma_f16(float& c0, float& c1, float& c2, float& c3,
                                        uint32_t a0, uint32_t a1, uint32_t a2, uint32_t a3,
                                        uint32_t b0, uint32_t b1) {
    asm volatile(
        "mma.sync.aligned.m16n8k16.row.col.f32.f16.f16.f32 "
        "{%0,%1,%2,%3}, {%4,%5,%6,%7}, {%8,%9}, {%0,%1,%2,%3};"
        : "+f"(c0), "+f"(c1), "+f"(c2), "+f"(c3)
        : "r"(a0), "r"(a1), "r"(a2), "r"(a3), "r"(b0), "r"(b1));
}
// f16-accum MMA (for S = theta.phi^T) — D comes out pre-packed for ex2h2
__device__ __forceinline__ void mma_f16h(uint32_t& d0, uint32_t& d1,
                                         uint32_t a0, uint32_t a1, uint32_t a2, uint32_t a3,
                                         uint32_t b0, uint32_t b1) {
    asm volatile(
        "mma.sync.aligned.m16n8k16.row.col.f16.f16.f16.f16 "
        "{%0,%1}, {%2,%3,%4,%5}, {%6,%7}, {%0,%1};"
        : "+r"(d0), "+r"(d1)
        : "r"(a0), "r"(a1), "r"(a2), "r"(a3), "r"(b0), "r"(b1));
}

// ===========================================================================
// Kernel A: projections (split per-matrix; proven R8 version).
// theta pre-scaled by log2(e); g written transposed fp16 [d][m].
// ===========================================================================
__global__ __launch_bounds__(128) void proj_kernel(
    const float* __restrict__ x,
    const float* __restrict__ tw, const float* __restrict__ tb,
    const float* __restrict__ pw, const float* __restrict__ pb,
    const float* __restrict__ gw, const float* __restrict__ gb)
{
    __shared__ __align__(16) float ws[NC * CI];
    __shared__ float bs[CI];

    int mat = blockIdx.y;
    const float* W  = (mat == 0) ? tw : ((mat == 1) ? pw : gw);
    const float* Bv = (mat == 0) ? tb : ((mat == 1) ? pb : gb);
    float scale = (mat == 0) ? LOG2E : 1.0f;

    int tid = threadIdx.x;
    for (int i = tid; i < CI * NC; i += 128) {
        int o = i >> 6, c = i & 63;
        ws[c * CI + o] = W[i] * scale;
    }
    if (tid < CI) bs[tid] = Bv[tid] * scale;
    __syncthreads();

    int bq = blockIdx.z;
    int n  = blockIdx.x * 128 + tid;
    int b  = bq >> 2, q = bq & 3, qr = q >> 1, qc = q & 1;
    int hh = n >> 6, ww = n & 63;

    const float* xp = x + (size_t)b * NC * HW + (qr * 64 + hh) * NW + (qc * 64 + ww);

    float acc[CI];
#pragma unroll
    for (int o = 0; o < CI; o++) acc[o] = bs[o];

    const float4* ws4 = (const float4*)ws;
#pragma unroll 4
    for (int c = 0; c < NC; c++) {
        float xv = xp[c * HW];
#pragma unroll
        for (int o4 = 0; o4 < 8; o4++) {
            float4 w = ws4[c * 8 + o4];
            acc[o4 * 4 + 0] += w.x * xv;
            acc[o4 * 4 + 1] += w.y * xv;
            acc[o4 * 4 + 2] += w.z * xv;
            acc[o4 * 4 + 3] += w.w * xv;
        }
    }

    if (mat == 2) {
        __half* op = g_gxT + (size_t)bq * CI * NN + n;
#pragma unroll
        for (int o = 0; o < CI; o++) op[(size_t)o * NN] = __float2half_rn(acc[o]);
    } else {
        __half* op = ((mat == 0) ? g_th : g_ph) + ((size_t)bq * NN + n) * CI;
#pragma unroll
        for (int o = 0; o < CI; o += 2) {
            __half2 h2 = __floats2half2_rn(acc[o], acc[o + 1]);
            *(__half2*)(op + o) = h2;
        }
    }
}

// ===========================================================================
// Kernel B: fp16 flash attention, M=32 rows per warp (two m16 A-groups),
// 4-warp CTAs (128 q-rows) -> 256 CTAs -> 2 CTAs/SM, 4 warps/SMSP.
// grid (32 q-tiles of 128 rows, 8 bq), block 128
// ===========================================================================
#define PH2 20                         // phi row stride in b32 words (16 data + 4 pad)
#define VT2 68                         // v^T row stride in b32 words (64 data + 4 pad)
#define PHI_WORDS (128 * PH2)          // 2560
#define VT_WORDS  (32 * VT2)           // 2176
#define BUF_WORDS (PHI_WORDS + VT_WORDS)  // 4736
#define PHI_BYTES (PHI_WORDS * 4)
#define BUF_BYTES (BUF_WORDS * 4)      // 18944
#define SMEM_TOTAL (2 * BUF_BYTES)     // 37888

__global__ void __launch_bounds__(128, 2) attn_mma_kernel()
{
    extern __shared__ uint32_t smw[];
    uint32_t sb = smem_to_u32(smw);
    int tid = threadIdx.x, wid = tid >> 5, lane = tid & 31;
    int g = lane >> 2, tig = lane & 3;               // row-group, thread-in-group
    int bq = blockIdx.y, qt = blockIdx.x;

    const __half* phg = g_ph  + (size_t)bq * NN * CI;
    const __half* vtg = g_gxT + (size_t)bq * CI * NN;

    // ---- theta A fragments: two 16-row groups (rows qt*128 + wid*32 + grp*16) ----
    uint32_t aS[2][2][4];
#pragma unroll
    for (int grp = 0; grp < 2; grp++) {
        const __half* thp = g_th + ((size_t)bq * NN + qt * 128 + wid * 32 + grp * 16) * CI;
#pragma unroll
        for (int kk = 0; kk < 2; kk++) {
            aS[grp][kk][0] = *(const uint32_t*)(thp + (size_t)g       * CI + (tig + 8 * kk) * 2);
            aS[grp][kk][1] = *(const uint32_t*)(thp + (size_t)(g + 8) * CI + (tig + 8 * kk) * 2);
            aS[grp][kk][2] = *(const uint32_t*)(thp + (size_t)g       * CI + (tig + 4 + 8 * kk) * 2);
            aS[grp][kk][3] = *(const uint32_t*)(thp + (size_t)(g + 8) * CI + (tig + 4 + 8 * kk) * 2);
        }
    }

    // ---- stage helper: tile t -> buffer buf (phi rows + v^T rows), cp.async ----
    // 1024 16B-chunks staged by 128 threads (8 each).
    auto stage = [&](int t, int buf) {
        uint32_t base = sb + (uint32_t)buf * BUF_BYTES;
        const __half* pg = phg + (size_t)t * 128 * CI;
#pragma unroll
        for (int cc = 0; cc < 4; cc++) {
            int idx = tid + cc * 128;            // 0..511 : phi chunks
            int row = idx >> 2, ch = idx & 3;    // phi: 128 rows x 4 chunks of 16B
            cp16(base + (uint32_t)(row * PH2 + ch * 4) * 4u, pg + (size_t)row * CI + ch * 8);
            int d = idx >> 4, kc = idx & 15;     // v^T: 32 rows x 16 chunks of 16B
            cp16(base + PHI_BYTES + (uint32_t)(d * VT2 + kc * 4) * 4u,
                 vtg + (size_t)d * NN + t * 128 + kc * 8);
        }
    };

    stage(0, 0);
    CP_COMMIT();

    float o[2][4][4];
#pragma unroll
    for (int grp = 0; grp < 2; grp++)
#pragma unroll
        for (int d = 0; d < 4; d++)
#pragma unroll
            for (int j = 0; j < 4; j++) o[grp][d][j] = 0.0f;
    float ls[2][2] = {{0.0f, 0.0f}, {0.0f, 0.0f}};

    for (int t = 0; t < NT; t++) {
        int cur = t & 1;
        if (t + 1 < NT) {
            stage(t + 1, cur ^ 1);
            CP_COMMIT();
            CP_WAIT(1);
        } else {
            CP_WAIT(0);
        }
        __syncthreads();

        const uint32_t* psw = smw + (size_t)cur * BUF_WORDS;
        const uint32_t* vtw = psw + PHI_WORDS;

#pragma unroll
        for (int nbp = 0; nbp < 8; nbp++) {
            // ---- load phi B-fragments ONCE for both key blocks ----
            const uint32_t* prow0 = psw + (nbp * 16 + g) * PH2;
            const uint32_t* prow1 = psw + (nbp * 16 + 8 + g) * PH2;
            uint32_t p00 = prow0[tig], p01 = prow0[tig + 4];
            uint32_t p02 = prow0[tig + 8], p03 = prow0[tig + 12];
            uint32_t p10 = prow1[tig], p11 = prow1[tig + 4];
            uint32_t p12 = prow1[tig + 8], p13 = prow1[tig + 12];

            uint32_t A[2][4];
#pragma unroll
            for (int grp = 0; grp < 2; grp++) {
                uint32_t s0 = 0, s1 = 0;
                mma_f16h(s0, s1, aS[grp][0][0], aS[grp][0][1], aS[grp][0][2], aS[grp][0][3],
                         p00, p01);
                mma_f16h(s0, s1, aS[grp][1][0], aS[grp][1][1], aS[grp][1][2], aS[grp][1][3],
                         p02, p03);
                uint32_t t0 = 0, t1 = 0;
                mma_f16h(t0, t1, aS[grp][0][0], aS[grp][0][1], aS[grp][0][2], aS[grp][0][3],
                         p10, p11);
                mma_f16h(t0, t1, aS[grp][1][0], aS[grp][1][1], aS[grp][1][2], aS[grp][1][3],
                         p12, p13);
                A[grp][0] = ex2h2(s0);   // row g,   keys of block 2nbp
                A[grp][1] = ex2h2(s1);   // row g+8, keys of block 2nbp
                A[grp][2] = ex2h2(t0);   // row g,   keys of block 2nbp+1
                A[grp][3] = ex2h2(t1);   // row g+8
                // row sums on fma pipe
                __half2 hg = __hadd2(*(__half2*)&A[grp][0], *(__half2*)&A[grp][2]);
                __half2 hb = __hadd2(*(__half2*)&A[grp][1], *(__half2*)&A[grp][3]);
                float2 fg = __half22float2(hg);
                float2 fb = __half22float2(hb);
                ls[grp][0] += fg.x + fg.y;
                ls[grp][1] += fb.x + fb.y;
            }
            // ---- load V B-fragments ONCE per d-block; feed both groups ----
#pragma unroll
            for (int d = 0; d < 4; d++) {
                const uint32_t* v = vtw + (g + 8 * d) * VT2 + nbp * 8;
                uint32_t vb0 = v[tig], vb1 = v[tig + 4];
                mma_f16(o[0][d][0], o[0][d][1], o[0][d][2], o[0][d][3],
                        A[0][0], A[0][1], A[0][2], A[0][3], vb0, vb1);
                mma_f16(o[1][d][0], o[1][d][1], o[1][d][2], o[1][d][3],
                        A[1][0], A[1][1], A[1][2], A[1][3], vb0, vb1);
            }
        }
        __syncthreads();   // all warps done with buf before it is restaged
    }

    // ---- finalize both groups ----
#pragma unroll
    for (int grp = 0; grp < 2; grp++) {
        float l0 = ls[grp][0], l1 = ls[grp][1];
        l0 += __shfl_xor_sync(0xFFFFFFFFu, l0, 1);
        l0 += __shfl_xor_sync(0xFFFFFFFFu, l0, 2);
        l1 += __shfl_xor_sync(0xFFFFFFFFu, l1, 1);
        l1 += __shfl_xor_sync(0xFFFFFFFFu, l1, 2);
        float inv0 = 1.0f / l0;
        float inv1 = 1.0f / l1;

        int row0 = qt * 128 + wid * 32 + grp * 16 + g;
        float* y0 = g_y + ((size_t)bq * NN + row0) * CI;
        float* y1 = y0 + 8 * CI;
#pragma unroll
        for (int j = 0; j < 4; j++) {
            *(float2*)(y0 + j * 8 + 2 * tig) =
                make_float2(o[grp][j][0] * inv0, o[grp][j][1] * inv0);
            *(float2*)(y1 + j * 8 + 2 * tig) =
                make_float2(o[grp][j][2] * inv1, o[grp][j][3] * inv1);
        }
    }
}

// ===========================================================================
// Kernel C: wy[bq][c][n] = w_w[c][:] . y[bq][n][:] + w_b[c]
// ===========================================================================
__global__ __launch_bounds__(256) void wy_kernel(
    const float* __restrict__ w_w, const float* __restrict__ w_b)
{
    __shared__ __align__(16) float ys[128 * CI];
    __shared__ __align__(16) float wws[NC * CI];

    int bq = blockIdx.y;
    int n0 = blockIdx.x * 128;
    int tid = threadIdx.x;

    for (int i = tid; i < NC * CI; i += 256) wws[i] = w_w[i];
    {
        const float4* src = (const float4*)(g_y + ((size_t)bq * NN + n0) * CI);
        float4* dst = (float4*)ys;
#pragma unroll
        for (int i = 0; i < 4; i++) dst[tid + i * 256] = src[tid + i * 256];
    }
    __syncthreads();

    int n = tid & 127;
    int chalf = (tid >> 7) * 32;

    float yr[CI];
#pragma unroll
    for (int o = 0; o < CI; o++) yr[o] = ys[n * CI + o];

    const float4* wws4 = (const float4*)wws;
    float* wyp = g_wy + (size_t)bq * NC * NN + n0 + n;
    for (int cc = 0; cc < 32; cc++) {
        int c = chalf + cc;
        float a = w_b[c];
#pragma unroll
        for (int o4 = 0; o4 < 8; o4++) {
            float4 w = wws4[c * 8 + o4];
            a += w.x * yr[o4 * 4 + 0] + w.y * yr[o4 * 4 + 1]
               + w.z * yr[o4 * 4 + 2] + w.w * yr[o4 * 4 + 3];
        }
        wyp[(size_t)c * NN] = a;
    }
}

// ===========================================================================
// Kernel E: per-(q,c) BN stats over (b,n) — 512 threads, float4 loads
// ===========================================================================
__global__ __launch_bounds__(512) void stats_kernel()
{
    int q = blockIdx.x >> 6, c = blockIdx.x & 63;
    int tid = threadIdx.x;
    float s = 0.0f, s2 = 0.0f;
#pragma unroll
    for (int b = 0; b < NB; b++) {
        const float4* p = (const float4*)(g_wy + (((size_t)(b * 4 + q) * NC) + c) * NN);
#pragma unroll
        for (int i = 0; i < 2; i++) {
            float4 v = p[tid + i * 512];
            s  += v.x + v.y + v.z + v.w;
            s2 += v.x * v.x + v.y * v.y + v.z * v.z + v.w * v.w;
        }
    }
    __shared__ float rs[512], rs2[512];
    rs[tid] = s; rs2[tid] = s2;
    __syncthreads();
    for (int st = 256; st > 0; st >>= 1) {
        if (tid < st) { rs[tid] += rs[tid + st]; rs2[tid] += rs2[tid + st]; }
        __syncthreads();
    }
    if (tid == 0) {
        float mu  = rs[0] * (1.0f / 8192.0f);
        float var = rs2[0] * (1.0f / 8192.0f) - mu * mu;
        g_mu[blockIdx.x]   = mu;
        g_rstd[blockIdx.x] = rsqrtf(var + 1e-5f);
    }
}

// ===========================================================================
// Kernel D: out = bn(wy)*gamma + beta + x
// ===========================================================================
__global__ __launch_bounds__(256) void out_kernel(
    const float* __restrict__ x,
    const float* __restrict__ gamma, const float* __restrict__ beta,
    float* __restrict__ out)
{
    int idx = blockIdx.x * 256 + threadIdx.x;
    int b   = idx >> 20;
    int rem = idx & 0xFFFFF;
    int c   = rem >> 14;
    int pos = rem & 0x3FFF;
    int h = pos >> 7, w = pos & 127;
    int q = ((h >> 6) << 1) | (w >> 6);
    int n = ((h & 63) << 6) | (w & 63);
    int bq = b * 4 + q;

    float v = g_wy[(((size_t)bq * NC) + c) * NN + n];
    int qc = q * NC + c;
    out[idx] = (v - g_mu[qc]) * g_rstd[qc] * gamma[c] + beta[c] + x[idx];
}

// ===========================================================================
// Launch
// ===========================================================================
extern "C" void kernel_launch(void* const* d_in, const int* in_sizes, int n_in,
                              void* d_out, int out_size)
{
    const float* x   = (const float*)d_in[0];
    const float* gw  = (const float*)d_in[1];
    const float* gb  = (const float*)d_in[2];
    const float* tw  = (const float*)d_in[3];
    const float* tb  = (const float*)d_in[4];
    const float* pw  = (const float*)d_in[5];
    const float* pb  = (const float*)d_in[6];
    const float* ww  = (const float*)d_in[7];
    const float* wb  = (const float*)d_in[8];
    const float* bng = (const float*)d_in[9];
    const float* bnb = (const float*)d_in[10];
    float* out = (float*)d_out;

    cudaFuncSetAttribute(attn_mma_kernel,
                         cudaFuncAttributeMaxDynamicSharedMemorySize, SMEM_TOTAL);

    dim3 gA(32, 3, 8);
    proj_kernel<<<gA, 128>>>(x, tw, tb, pw, pb, gw, gb);

    dim3 gB(32, 8);
    attn_mma_kernel<<<gB, 128, SMEM_TOTAL>>>();

    dim3 gC(32, 8);
    wy_kernel<<<gC, 256>>>(ww, wb);

    stats_kernel<<<256, 512>>>();

    out_kernel<<<8192, 256>>>(x, bng, bnb, out);
}